// round 7
// baseline (speedup 1.0000x reference)
#include <cuda_runtime.h>
#include <cuda_fp16.h>
#include <stdint.h>

#define NN   100000
#define MAXE 1600000

// ---------------- device scratch (static; no allocations) ----------------
__device__ __align__(16) __half2 g_tf16[(size_t)NN * 64];  // fp16 prescaled t~ (all layers)
__device__ __align__(16) float   g_h[(size_t)NN * 128];    // layer outputs (fp32)
__device__ float g_dinv[NN];
__device__ float g_as[NN];
__device__ float g_bs[NN];
__device__ int   g_cnt[NN];
__device__ int   g_rowstart[NN + 1];
__device__ int   g_fill[NN];
__device__ int   g_bsum[256];
__device__ int   g_csr[MAXE];
__device__ int   g_is64;

// ---------------- edge index accessors (dtype-agnostic) ----------------
__device__ __forceinline__ int esrc(const int* __restrict__ ei, int e) {
    return g_is64 ? ei[2 * e] : ei[e];
}
__device__ __forceinline__ int edst(const int* __restrict__ ei, int e, int E) {
    return g_is64 ? ei[2 * (E + e)] : ei[E + e];
}

__global__ void k_detect(const int* __restrict__ ei) {
    int odd_nonzero = 0;
    for (int i = threadIdx.x; i < 256; i += 32)
        if (ei[2 * i + 1] != 0) odd_nonzero = 1;
    unsigned m = __ballot_sync(0xFFFFFFFFu, odd_nonzero);
    if (threadIdx.x == 0) g_is64 = (m == 0) ? 1 : 0;
}

// ---------------- graph preprocessing ----------------
__global__ void k_zero_cnt() {
    int i = blockIdx.x * blockDim.x + threadIdx.x;
    if (i < NN) g_cnt[i] = 0;
}

__global__ void k_hist(const int* __restrict__ ei, int E) {
    int e = blockIdx.x * blockDim.x + threadIdx.x;
    if (e < E) atomicAdd(&g_cnt[edst(ei, e, E)], 1);
}

__global__ void k_scan1() {
    __shared__ int sh[1024];
    int i = blockIdx.x * 1024 + threadIdx.x;
    int v = (i < NN) ? g_cnt[i] : 0;
    sh[threadIdx.x] = v;
    __syncthreads();
    for (int off = 1; off < 1024; off <<= 1) {
        int t = (threadIdx.x >= off) ? sh[threadIdx.x - off] : 0;
        __syncthreads();
        sh[threadIdx.x] += t;
        __syncthreads();
    }
    if (i < NN) g_rowstart[i + 1] = sh[threadIdx.x];
    if (threadIdx.x == 1023) g_bsum[blockIdx.x] = sh[1023];
    if (i == 0) g_rowstart[0] = 0;
}

__global__ void k_scan2(int nblocks) {
    if (threadIdx.x == 0 && blockIdx.x == 0) {
        int acc = 0;
        for (int b = 0; b < nblocks; b++) {
            int v = g_bsum[b];
            g_bsum[b] = acc;
            acc += v;
        }
    }
}

__global__ void k_scan3() {
    int i = blockIdx.x * 1024 + threadIdx.x;
    if (i < NN) g_rowstart[i + 1] += g_bsum[blockIdx.x];
}

__global__ void k_prep() {
    int i = blockIdx.x * blockDim.x + threadIdx.x;
    if (i < NN) {
        g_fill[i] = g_rowstart[i];
        g_dinv[i] = rsqrtf((float)g_cnt[i] + 1.0f);
    }
}

__global__ void k_scatter(const int* __restrict__ ei, int E) {
    int e = blockIdx.x * blockDim.x + threadIdx.x;
    if (e < E) {
        int d = edst(ei, e, E);
        int pos = atomicAdd(&g_fill[d], 1);
        g_csr[pos] = esrc(ei, e);
    }
}

// ---- split-fp16 tensor GEMM (3-term, ~fp32 accurate): t~=(X@W)*dinv, fp16 out ----
// Block tile: 128 rows x M cols, 256 threads (8 warps). K staged by BK=32.
template <int K, int M>
__global__ void k_gemm_mma(const float* __restrict__ Xext,
                           const float* __restrict__ W, int n) {
    constexpr int BK  = 32;
    constexpr int STG = K / BK;
    constexpr int AP  = BK + 8;
    constexpr int WC  = (M >= 128) ? 2 : 1;
    constexpr int WR  = 8 / WC;
    constexpr int WROWS = 128 / WR;
    constexpr int WCOLS = M / WC;
    constexpr int MT  = WROWS / 16;
    constexpr int NT  = WCOLS / 8;

    __shared__ __align__(16) __half Ah[128 * AP];
    __shared__ __align__(16) __half Al[128 * AP];
    __shared__ __align__(16) __half Bh[M * AP];
    __shared__ __align__(16) __half Bl[M * AP];

    const float* __restrict__ X = Xext ? Xext : g_h;
    int t    = threadIdx.x;
    int warp = t >> 5, lane = t & 31;
    int g    = lane >> 2, tg = lane & 3;
    int wm   = (warp % WR) * WROWS;
    int wn   = (warp / WR) * WCOLS;
    int base = blockIdx.x * 128;

    float acc[MT][NT][4];
#pragma unroll
    for (int mt = 0; mt < MT; mt++)
#pragma unroll
        for (int nt = 0; nt < NT; nt++)
#pragma unroll
            for (int j = 0; j < 4; j++) acc[mt][nt][j] = 0.f;

    for (int s = 0; s < STG; s++) {
        int k0 = s * BK;
#pragma unroll
        for (int j = 0; j < 4; j++) {
            int idx = t + j * 256;
            int r = idx >> 3, c4 = idx & 7;
            float4 v = make_float4(0.f, 0.f, 0.f, 0.f);
            if (base + r < n)
                v = *(const float4*)(X + (size_t)(base + r) * K + k0 + c4 * 4);
            __half hx = __float2half_rn(v.x), hy = __float2half_rn(v.y);
            __half hz = __float2half_rn(v.z), hw = __float2half_rn(v.w);
            __half2 h0 = __halves2half2(hx, hy);
            __half2 h1 = __halves2half2(hz, hw);
            __half2 l0 = __floats2half2_rn(v.x - __half2float(hx), v.y - __half2float(hy));
            __half2 l1 = __floats2half2_rn(v.z - __half2float(hz), v.w - __half2float(hw));
            uint2 uh, ul;
            uh.x = *(unsigned*)&h0; uh.y = *(unsigned*)&h1;
            ul.x = *(unsigned*)&l0; ul.y = *(unsigned*)&l1;
            *(uint2*)&Ah[r * AP + c4 * 4] = uh;
            *(uint2*)&Al[r * AP + c4 * 4] = ul;
        }
        constexpr int WE = (BK * M) / 256;
#pragma unroll
        for (int j = 0; j < WE; j++) {
            int idx = t + j * 256;
            int k = idx / M, m = idx % M;
            float w = W[(size_t)(k0 + k) * M + m];
            __half wh = __float2half_rn(w);
            Bh[m * AP + k] = wh;
            Bl[m * AP + k] = __float2half_rn(w - __half2float(wh));
        }
        __syncthreads();

#pragma unroll
        for (int kk = 0; kk < BK; kk += 16) {
            unsigned ah[MT][4], al[MT][4], bh[NT][2], bl[NT][2];
#pragma unroll
            for (int mt = 0; mt < MT; mt++) {
                int off = (wm + mt * 16 + g) * AP + kk + tg * 2;
                ah[mt][0] = *(const unsigned*)&Ah[off];
                ah[mt][1] = *(const unsigned*)&Ah[off + 8 * AP];
                ah[mt][2] = *(const unsigned*)&Ah[off + 8];
                ah[mt][3] = *(const unsigned*)&Ah[off + 8 * AP + 8];
                al[mt][0] = *(const unsigned*)&Al[off];
                al[mt][1] = *(const unsigned*)&Al[off + 8 * AP];
                al[mt][2] = *(const unsigned*)&Al[off + 8];
                al[mt][3] = *(const unsigned*)&Al[off + 8 * AP + 8];
            }
#pragma unroll
            for (int nt = 0; nt < NT; nt++) {
                int off = (wn + nt * 8 + g) * AP + kk + tg * 2;
                bh[nt][0] = *(const unsigned*)&Bh[off];
                bh[nt][1] = *(const unsigned*)&Bh[off + 8];
                bl[nt][0] = *(const unsigned*)&Bl[off];
                bl[nt][1] = *(const unsigned*)&Bl[off + 8];
            }
#define MMA(AC, A0, A1, A2, A3, B0, B1)                                       \
    asm volatile(                                                             \
        "mma.sync.aligned.m16n8k16.row.col.f32.f16.f16.f32 "                  \
        "{%0,%1,%2,%3},{%4,%5,%6,%7},{%8,%9},{%0,%1,%2,%3};"                  \
        : "+f"(AC[0]), "+f"(AC[1]), "+f"(AC[2]), "+f"(AC[3])                  \
        : "r"(A0), "r"(A1), "r"(A2), "r"(A3), "r"(B0), "r"(B1))
#pragma unroll
            for (int mt = 0; mt < MT; mt++)
#pragma unroll
                for (int nt = 0; nt < NT; nt++) {
                    MMA(acc[mt][nt], ah[mt][0], ah[mt][1], ah[mt][2], ah[mt][3],
                        bh[nt][0], bh[nt][1]);
                    MMA(acc[mt][nt], ah[mt][0], ah[mt][1], ah[mt][2], ah[mt][3],
                        bl[nt][0], bl[nt][1]);
                    MMA(acc[mt][nt], al[mt][0], al[mt][1], al[mt][2], al[mt][3],
                        bh[nt][0], bh[nt][1]);
                }
#undef MMA
        }
        __syncthreads();
    }

#pragma unroll
    for (int mt = 0; mt < MT; mt++) {
        int r0 = base + wm + mt * 16 + g;
        int r1 = r0 + 8;
        float s0 = (r0 < n) ? g_dinv[r0] : 0.f;
        float s1 = (r1 < n) ? g_dinv[r1] : 0.f;
#pragma unroll
        for (int nt = 0; nt < NT; nt++) {
            int c = wn + nt * 8 + tg * 2;
            if (r0 < n)
                g_tf16[(size_t)r0 * (M / 2) + (c >> 1)] =
                    __floats2half2_rn(acc[mt][nt][0] * s0, acc[mt][nt][1] * s0);
            if (r1 < n)
                g_tf16[(size_t)r1 * (M / 2) + (c >> 1)] =
                    __floats2half2_rn(acc[mt][nt][2] * s1, acc[mt][nt][3] * s1);
        }
    }
}

// ---------- aggregation over fp16 prescaled rows (layers 1,2) ----------
template <int M>
__global__ void k_agg_h(const float* __restrict__ bias) {
    constexpr int V2 = M / 64;
    int gw   = (blockIdx.x * blockDim.x + threadIdx.x) >> 5;
    int lane = threadIdx.x & 31;
    if (gw >= NN) return;

    float dd = g_dinv[gw];
    int rs = g_rowstart[gw];
    int re = g_rowstart[gw + 1];

    float acc[2 * V2];
#pragma unroll
    for (int v = 0; v < 2 * V2; v++) acc[v] = 0.f;

    int e = rs;
    for (; e + 2 <= re; e += 2) {       // unroll x2: paired row loads for MLP
        int s0 = g_csr[e], s1 = g_csr[e + 1];
        const __half2* r0 = g_tf16 + (size_t)s0 * (M / 2) + lane * V2;
        const __half2* r1 = g_tf16 + (size_t)s1 * (M / 2) + lane * V2;
        if (V2 == 2) {
            float2 a0 = *(const float2*)r0;
            float2 a1 = *(const float2*)r1;
            float2 f00 = __half22float2(*(__half2*)&a0.x);
            float2 f01 = __half22float2(*(__half2*)&a0.y);
            float2 f10 = __half22float2(*(__half2*)&a1.x);
            float2 f11 = __half22float2(*(__half2*)&a1.y);
            acc[0] += f00.x + f10.x; acc[1] += f00.y + f10.y;
            acc[2] += f01.x + f11.x; acc[3] += f01.y + f11.y;
        } else {
            float2 f0 = __half22float2(r0[0]);
            float2 f1 = __half22float2(r1[0]);
            acc[0] += f0.x + f1.x; acc[1] += f0.y + f1.y;
        }
    }
    for (; e < re; e++) {
        int s = g_csr[e];
        const __half2* row = g_tf16 + (size_t)s * (M / 2) + lane * V2;
#pragma unroll
        for (int v = 0; v < V2; v++) {
            float2 f = __half22float2(row[v]);
            acc[2 * v] += f.x; acc[2 * v + 1] += f.y;
        }
    }
    {   // self loop
        const __half2* row = g_tf16 + (size_t)gw * (M / 2) + lane * V2;
#pragma unroll
        for (int v = 0; v < V2; v++) {
            float2 f = __half22float2(row[v]);
            acc[2 * v] += f.x; acc[2 * v + 1] += f.y;
        }
    }
#pragma unroll
    for (int v = 0; v < 2 * V2; v++) {
        float o = acc[v] * dd + bias[lane * 2 * V2 + v];
        g_h[(size_t)gw * M + lane * 2 * V2 + v] = fmaxf(o, 0.f);
    }
}

// ---- layer-3 aggregation (fp16 t~, 64B/edge) fused with node scoring ----
__global__ void k_agg3_score(const float* __restrict__ bias,
                             const float* __restrict__ Wc) {
    const __half* __restrict__ T = (const __half*)g_tf16;
    int gw   = (blockIdx.x * blockDim.x + threadIdx.x) >> 5;
    int lane = threadIdx.x & 31;
    if (gw >= NN) return;

    float dd = g_dinv[gw];
    int rs = g_rowstart[gw];
    int re = g_rowstart[gw + 1];

    float acc = 0.f;
    int e = rs;
    for (; e + 2 <= re; e += 2) {
        int s0 = g_csr[e], s1 = g_csr[e + 1];
        float v0 = __half2float(T[(size_t)s0 * 32 + lane]);
        float v1 = __half2float(T[(size_t)s1 * 32 + lane]);
        acc += v0 + v1;
    }
    for (; e < re; e++)
        acc += __half2float(T[(size_t)g_csr[e] * 32 + lane]);
    acc += __half2float(T[(size_t)gw * 32 + lane]);

    float o = fmaxf(acc * dd + bias[lane], 0.f);
    float p = o * Wc[lane];
    float q = o * Wc[32 + lane];
#pragma unroll
    for (int off = 16; off; off >>= 1) {
        p += __shfl_xor_sync(0xFFFFFFFFu, p, off);
        q += __shfl_xor_sync(0xFFFFFFFFu, q, off);
    }
    if (lane == 0) { g_as[gw] = p; g_bs[gw] = q; }
}

__global__ void k_edgeout(const int* __restrict__ ei,
                          const float* __restrict__ bc,
                          float* __restrict__ out, int E) {
    int e = blockIdx.x * blockDim.x + threadIdx.x;
    if (e < E) out[e] = g_as[esrc(ei, e)] + g_bs[edst(ei, e, E)] + bc[0];
}

// ---------------- launch ----------------
extern "C" void kernel_launch(void* const* d_in, const int* in_sizes, int n_in,
                              void* d_out, int out_size) {
    const float* x   = (const float*)d_in[0];
    const int*   ei  = (const int*)d_in[1];
    const float* W1  = (const float*)d_in[2];
    const float* b1  = (const float*)d_in[3];
    const float* W2  = (const float*)d_in[4];
    const float* b2  = (const float*)d_in[5];
    const float* W3  = (const float*)d_in[6];
    const float* b3  = (const float*)d_in[7];
    const float* Wc  = (const float*)d_in[8];
    const float* bc  = (const float*)d_in[9];
    float*       out = (float*)d_out;

    int E = in_sizes[1] / 2;

    int nbN = (NN + 255) / 256;
    int nbE = (E + 255) / 256;
    int sb  = (NN + 1023) / 1024;
    int nbW = (NN * 32 + 255) / 256;    // warp-per-node kernels
    int nbM = (NN + 127) / 128;         // mma GEMM blocks

    // dtype probe + CSR build + normalization
    k_detect<<<1, 32>>>(ei);
    k_zero_cnt<<<nbN, 256>>>();
    k_hist<<<nbE, 256>>>(ei, E);
    k_scan1<<<sb, 1024>>>();
    k_scan2<<<1, 32>>>(sb);
    k_scan3<<<sb, 1024>>>();
    k_prep<<<nbN, 256>>>();
    k_scatter<<<nbE, 256>>>(ei, E);

    // layer 1: 128 -> 128 (split-fp16 tensor GEMM, fp16 prescaled gather)
    k_gemm_mma<128, 128><<<nbM, 256>>>(x, W1, NN);
    k_agg_h<128><<<nbW, 256>>>(b1);
    // layer 2: 128 -> 64
    k_gemm_mma<128, 64><<<nbM, 256>>>(nullptr, W2, NN);
    k_agg_h<64><<<nbW, 256>>>(b2);
    // layer 3: 64 -> 32 (split-fp16 tensor GEMM, fp16 gather + fused scoring)
    k_gemm_mma<64, 32><<<nbM, 256>>>(nullptr, W3, NN);
    k_agg3_score<<<nbW, 256>>>(b3, Wc);

    // edge scoring
    k_edgeout<<<nbE, 256>>>(ei, bc, out, E);
}

// round 8
// speedup vs baseline: 1.0464x; 1.0464x over previous
#include <cuda_runtime.h>
#include <cuda_fp16.h>
#include <stdint.h>

#define NN   100000
#define MAXE 1600000

// ---------------- device scratch (static; no allocations) ----------------
__device__ __align__(16) __half2 g_tf16[(size_t)NN * 64];  // fp16 t~ (all layers)
__device__ __align__(16) float   g_h[(size_t)NN * 128];    // layer outputs (fp32)
__device__ float g_dinv[NN];
__device__ float g_as[NN];
__device__ float g_bs[NN];
__device__ int   g_cnt[NN];
__device__ int   g_rowstart[NN + 1];
__device__ int   g_fill[NN];
__device__ int   g_bsum[256];
__device__ int   g_csr[MAXE];

// ---- per-block edge-index dtype probe (replaces global detect kernel) ----
// int64 little-endian => odd int32 slots (high words of small ids) are all 0.
__device__ __forceinline__ int probe_is64(const int* __restrict__ ei,
                                          int* s_is64) {
    if (threadIdx.x < 32) {
        int nz = 0;
        for (int i = threadIdx.x; i < 64; i += 32)
            if (ei[2 * i + 1] != 0) nz = 1;
        unsigned m = __ballot_sync(0xFFFFFFFFu, nz);
        if (threadIdx.x == 0) *s_is64 = (m == 0) ? 1 : 0;
    }
    __syncthreads();
    return *s_is64;
}
__device__ __forceinline__ int esrc(const int* __restrict__ ei, int e, int is64) {
    return is64 ? ei[2 * e] : ei[e];
}
__device__ __forceinline__ int edst(const int* __restrict__ ei, int e, int E, int is64) {
    return is64 ? ei[2 * (E + e)] : ei[E + e];
}

// ---------------- graph preprocessing ----------------
__global__ void k_hist(const int* __restrict__ ei, int E) {
    __shared__ int s_is64;
    int is64 = probe_is64(ei, &s_is64);
    int e = blockIdx.x * blockDim.x + threadIdx.x;
    if (e < E) atomicAdd(&g_cnt[edst(ei, e, E, is64)], 1);
}

// per-1024-chunk inclusive scan; writes rowstart[i+1] (pre-offset) + partials
__global__ void k_scan_a() {
    __shared__ int sh[1024];
    int i = blockIdx.x * 1024 + threadIdx.x;
    int v = (i < NN) ? g_cnt[i] : 0;
    sh[threadIdx.x] = v;
    __syncthreads();
    for (int off = 1; off < 1024; off <<= 1) {
        int t = (threadIdx.x >= off) ? sh[threadIdx.x - off] : 0;
        __syncthreads();
        sh[threadIdx.x] += t;
        __syncthreads();
    }
    if (i < NN) g_rowstart[i + 1] = sh[threadIdx.x];
    if (threadIdx.x == 1023) g_bsum[blockIdx.x] = sh[1023];
}

// add cross-block offsets (each block redundantly scans the 98 partials),
// and produce fill[] + dinv[] (folds old scan2+scan3+prep into one kernel)
__global__ void k_scan_b(int nblocks) {
    __shared__ int soff;
    if (threadIdx.x == 0) {
        int acc = 0;
        for (int b = 0; b < (int)blockIdx.x && b < nblocks; b++) acc += g_bsum[b];
        soff = acc;
    }
    __syncthreads();
    int off = soff;
    int i = blockIdx.x * 1024 + threadIdx.x;
    if (i < NN) {
        int prev = (threadIdx.x == 0) ? 0 : g_rowstart[i];  // pre-offset value
        int fin_prev = prev + off;
        g_fill[i] = fin_prev;
        g_rowstart[i + 1] += off;
        g_dinv[i] = rsqrtf((float)g_cnt[i] + 1.0f);
        if (i == 0) g_rowstart[0] = 0;
    }
}

__global__ void k_scatter(const int* __restrict__ ei, int E) {
    __shared__ int s_is64;
    int is64 = probe_is64(ei, &s_is64);
    int e = blockIdx.x * blockDim.x + threadIdx.x;
    if (e < E) {
        int d = edst(ei, e, E, is64);
        int pos = atomicAdd(&g_fill[d], 1);
        g_csr[pos] = esrc(ei, e, is64);
    }
}

// ---- split-fp16 tensor GEMM (3-term, ~fp32 accurate): t~ = (X@W)[*dinv] ----
// Block tile: 128 rows x M cols, 256 threads. PRESC: scale rows by dinv.
template <int K, int M, int PRESC>
__global__ void k_gemm_mma(const float* __restrict__ Xext,
                           const float* __restrict__ W, int n) {
    constexpr int BK  = 32;
    constexpr int STG = K / BK;
    constexpr int AP  = BK + 8;
    constexpr int WC  = (M >= 128) ? 2 : 1;
    constexpr int WR  = 8 / WC;
    constexpr int WROWS = 128 / WR;
    constexpr int WCOLS = M / WC;
    constexpr int MT  = WROWS / 16;
    constexpr int NT  = WCOLS / 8;

    __shared__ __align__(16) __half Ah[128 * AP];
    __shared__ __align__(16) __half Al[128 * AP];
    __shared__ __align__(16) __half Bh[M * AP];
    __shared__ __align__(16) __half Bl[M * AP];

    const float* __restrict__ X = Xext ? Xext : g_h;
    int t    = threadIdx.x;
    int warp = t >> 5, lane = t & 31;
    int g    = lane >> 2, tg = lane & 3;
    int wm   = (warp % WR) * WROWS;
    int wn   = (warp / WR) * WCOLS;
    int base = blockIdx.x * 128;

    float acc[MT][NT][4];
#pragma unroll
    for (int mt = 0; mt < MT; mt++)
#pragma unroll
        for (int nt = 0; nt < NT; nt++)
#pragma unroll
            for (int j = 0; j < 4; j++) acc[mt][nt][j] = 0.f;

    for (int s = 0; s < STG; s++) {
        int k0 = s * BK;
#pragma unroll
        for (int j = 0; j < 4; j++) {
            int idx = t + j * 256;
            int r = idx >> 3, c4 = idx & 7;
            float4 v = make_float4(0.f, 0.f, 0.f, 0.f);
            if (base + r < n)
                v = *(const float4*)(X + (size_t)(base + r) * K + k0 + c4 * 4);
            __half hx = __float2half_rn(v.x), hy = __float2half_rn(v.y);
            __half hz = __float2half_rn(v.z), hw = __float2half_rn(v.w);
            __half2 h0 = __halves2half2(hx, hy);
            __half2 h1 = __halves2half2(hz, hw);
            __half2 l0 = __floats2half2_rn(v.x - __half2float(hx), v.y - __half2float(hy));
            __half2 l1 = __floats2half2_rn(v.z - __half2float(hz), v.w - __half2float(hw));
            uint2 uh, ul;
            uh.x = *(unsigned*)&h0; uh.y = *(unsigned*)&h1;
            ul.x = *(unsigned*)&l0; ul.y = *(unsigned*)&l1;
            *(uint2*)&Ah[r * AP + c4 * 4] = uh;
            *(uint2*)&Al[r * AP + c4 * 4] = ul;
        }
        constexpr int WE = (BK * M) / 256;
#pragma unroll
        for (int j = 0; j < WE; j++) {
            int idx = t + j * 256;
            int k = idx / M, m = idx % M;
            float w = W[(size_t)(k0 + k) * M + m];
            __half wh = __float2half_rn(w);
            Bh[m * AP + k] = wh;
            Bl[m * AP + k] = __float2half_rn(w - __half2float(wh));
        }
        __syncthreads();

#pragma unroll
        for (int kk = 0; kk < BK; kk += 16) {
            unsigned ah[MT][4], al[MT][4], bh[NT][2], bl[NT][2];
#pragma unroll
            for (int mt = 0; mt < MT; mt++) {
                int off = (wm + mt * 16 + g) * AP + kk + tg * 2;
                ah[mt][0] = *(const unsigned*)&Ah[off];
                ah[mt][1] = *(const unsigned*)&Ah[off + 8 * AP];
                ah[mt][2] = *(const unsigned*)&Ah[off + 8];
                ah[mt][3] = *(const unsigned*)&Ah[off + 8 * AP + 8];
                al[mt][0] = *(const unsigned*)&Al[off];
                al[mt][1] = *(const unsigned*)&Al[off + 8 * AP];
                al[mt][2] = *(const unsigned*)&Al[off + 8];
                al[mt][3] = *(const unsigned*)&Al[off + 8 * AP + 8];
            }
#pragma unroll
            for (int nt = 0; nt < NT; nt++) {
                int off = (wn + nt * 8 + g) * AP + kk + tg * 2;
                bh[nt][0] = *(const unsigned*)&Bh[off];
                bh[nt][1] = *(const unsigned*)&Bh[off + 8];
                bl[nt][0] = *(const unsigned*)&Bl[off];
                bl[nt][1] = *(const unsigned*)&Bl[off + 8];
            }
#define MMA(AC, A0, A1, A2, A3, B0, B1)                                       \
    asm volatile(                                                             \
        "mma.sync.aligned.m16n8k16.row.col.f32.f16.f16.f32 "                  \
        "{%0,%1,%2,%3},{%4,%5,%6,%7},{%8,%9},{%0,%1,%2,%3};"                  \
        : "+f"(AC[0]), "+f"(AC[1]), "+f"(AC[2]), "+f"(AC[3])                  \
        : "r"(A0), "r"(A1), "r"(A2), "r"(A3), "r"(B0), "r"(B1))
#pragma unroll
            for (int mt = 0; mt < MT; mt++)
#pragma unroll
                for (int nt = 0; nt < NT; nt++) {
                    MMA(acc[mt][nt], ah[mt][0], ah[mt][1], ah[mt][2], ah[mt][3],
                        bh[nt][0], bh[nt][1]);
                    MMA(acc[mt][nt], ah[mt][0], ah[mt][1], ah[mt][2], ah[mt][3],
                        bl[nt][0], bl[nt][1]);
                    MMA(acc[mt][nt], al[mt][0], al[mt][1], al[mt][2], al[mt][3],
                        bh[nt][0], bh[nt][1]);
                }
#undef MMA
        }
        __syncthreads();
    }

#pragma unroll
    for (int mt = 0; mt < MT; mt++) {
        int r0 = base + wm + mt * 16 + g;
        int r1 = r0 + 8;
        float s0 = PRESC ? ((r0 < n) ? g_dinv[r0] : 0.f) : 1.f;
        float s1 = PRESC ? ((r1 < n) ? g_dinv[r1] : 0.f) : 1.f;
#pragma unroll
        for (int nt = 0; nt < NT; nt++) {
            int c = wn + nt * 8 + tg * 2;
            if (r0 < n)
                g_tf16[(size_t)r0 * (M / 2) + (c >> 1)] =
                    __floats2half2_rn(acc[mt][nt][0] * s0, acc[mt][nt][1] * s0);
            if (r1 < n)
                g_tf16[(size_t)r1 * (M / 2) + (c >> 1)] =
                    __floats2half2_rn(acc[mt][nt][2] * s1, acc[mt][nt][3] * s1);
        }
    }
}

// ---------- aggregation over fp16 rows. SCALED: t~ already has dinv[s] ----------
template <int M, int SCALED>
__global__ void k_agg_h(const float* __restrict__ bias) {
    constexpr int V2 = M / 64;
    int gw   = (blockIdx.x * blockDim.x + threadIdx.x) >> 5;
    int lane = threadIdx.x & 31;
    if (gw >= NN) return;

    float dd = g_dinv[gw];
    int rs = g_rowstart[gw];
    int re = g_rowstart[gw + 1];

    float acc[2 * V2];
#pragma unroll
    for (int v = 0; v < 2 * V2; v++) acc[v] = 0.f;

    int e = rs;
    for (; e + 2 <= re; e += 2) {
        int s0 = g_csr[e], s1 = g_csr[e + 1];
        float w0 = SCALED ? 1.f : g_dinv[s0];
        float w1 = SCALED ? 1.f : g_dinv[s1];
        const __half2* r0 = g_tf16 + (size_t)s0 * (M / 2) + lane * V2;
        const __half2* r1 = g_tf16 + (size_t)s1 * (M / 2) + lane * V2;
        if (V2 == 2) {
            float2 a0 = *(const float2*)r0;
            float2 a1 = *(const float2*)r1;
            float2 f00 = __half22float2(*(__half2*)&a0.x);
            float2 f01 = __half22float2(*(__half2*)&a0.y);
            float2 f10 = __half22float2(*(__half2*)&a1.x);
            float2 f11 = __half22float2(*(__half2*)&a1.y);
            acc[0] += f00.x * w0 + f10.x * w1; acc[1] += f00.y * w0 + f10.y * w1;
            acc[2] += f01.x * w0 + f11.x * w1; acc[3] += f01.y * w0 + f11.y * w1;
        } else {
            float2 f0 = __half22float2(r0[0]);
            float2 f1 = __half22float2(r1[0]);
            acc[0] += f0.x * w0 + f1.x * w1; acc[1] += f0.y * w0 + f1.y * w1;
        }
    }
    for (; e < re; e++) {
        int s = g_csr[e];
        float w = SCALED ? 1.f : g_dinv[s];
        const __half2* row = g_tf16 + (size_t)s * (M / 2) + lane * V2;
#pragma unroll
        for (int v = 0; v < V2; v++) {
            float2 f = __half22float2(row[v]);
            acc[2 * v] += f.x * w; acc[2 * v + 1] += f.y * w;
        }
    }
    {   // self loop
        float w = SCALED ? 1.f : dd;
        const __half2* row = g_tf16 + (size_t)gw * (M / 2) + lane * V2;
#pragma unroll
        for (int v = 0; v < V2; v++) {
            float2 f = __half22float2(row[v]);
            acc[2 * v] += f.x * w; acc[2 * v + 1] += f.y * w;
        }
    }
#pragma unroll
    for (int v = 0; v < 2 * V2; v++) {
        float o = acc[v] * dd + bias[lane * 2 * V2 + v];
        g_h[(size_t)gw * M + lane * 2 * V2 + v] = fmaxf(o, 0.f);
    }
}

// ---- layer-3 agg (fp16, 2 edges/warp via half-warps) fused with scoring ----
__global__ void k_agg3_score(const float* __restrict__ bias,
                             const float* __restrict__ Wc) {
    int gw   = (blockIdx.x * blockDim.x + threadIdx.x) >> 5;
    int lane = threadIdx.x & 31;
    if (gw >= NN) return;

    int half = lane >> 4;
    int hl   = lane & 15;        // col pair index: cols 2*hl, 2*hl+1

    float dd = g_dinv[gw];
    int rs = g_rowstart[gw];
    int re = g_rowstart[gw + 1];

    float a0 = 0.f, a1 = 0.f;
    for (int e = rs + half; e < re; e += 2) {
        int s = g_csr[e];
        float2 f = __half22float2(g_tf16[(size_t)s * 16 + hl]);
        a0 += f.x; a1 += f.y;
    }
    // combine the two half-warps (lanes 0-15 get totals)
    a0 += __shfl_down_sync(0xFFFFFFFFu, a0, 16);
    a1 += __shfl_down_sync(0xFFFFFFFFu, a1, 16);

    // self loop + epilogue on lanes 0-15
    float2 fs = __half22float2(g_tf16[(size_t)gw * 16 + hl]);
    a0 += fs.x; a1 += fs.y;
    float o0 = fmaxf(a0 * dd + bias[2 * hl], 0.f);
    float o1 = fmaxf(a1 * dd + bias[2 * hl + 1], 0.f);
    float p = o0 * Wc[2 * hl] + o1 * Wc[2 * hl + 1];
    float q = o0 * Wc[32 + 2 * hl] + o1 * Wc[32 + 2 * hl + 1];
#pragma unroll
    for (int off = 8; off; off >>= 1) {
        p += __shfl_xor_sync(0xFFFFFFFFu, p, off);
        q += __shfl_xor_sync(0xFFFFFFFFu, q, off);
    }
    if (lane == 0) { g_as[gw] = p; g_bs[gw] = q; }
}

__global__ void k_edgeout(const int* __restrict__ ei,
                          const float* __restrict__ bc,
                          float* __restrict__ out, int E) {
    __shared__ int s_is64;
    int is64 = probe_is64(ei, &s_is64);
    int e = blockIdx.x * blockDim.x + threadIdx.x;
    if (e < E)
        out[e] = g_as[esrc(ei, e, is64)] + g_bs[edst(ei, e, E, is64)] + bc[0];
}

// ---------------- launch ----------------
extern "C" void kernel_launch(void* const* d_in, const int* in_sizes, int n_in,
                              void* d_out, int out_size) {
    const float* x   = (const float*)d_in[0];
    const int*   ei  = (const int*)d_in[1];
    const float* W1  = (const float*)d_in[2];
    const float* b1  = (const float*)d_in[3];
    const float* W2  = (const float*)d_in[4];
    const float* b2  = (const float*)d_in[5];
    const float* W3  = (const float*)d_in[6];
    const float* b3  = (const float*)d_in[7];
    const float* Wc  = (const float*)d_in[8];
    const float* bc  = (const float*)d_in[9];
    float*       out = (float*)d_out;

    int E = in_sizes[1] / 2;

    int nbE = (E + 255) / 256;
    int sb  = (NN + 1023) / 1024;
    int nbW = (NN * 32 + 255) / 256;    // warp-per-node kernels
    int nbM = (NN + 127) / 128;         // mma GEMM blocks

    // fork: layer-1 GEMM (no prescale -> independent of CSR build) on side stream
    cudaStream_t s2;
    cudaEvent_t evFork, evJoin;
    cudaStreamCreateWithFlags(&s2, cudaStreamNonBlocking);
    cudaEventCreateWithFlags(&evFork, cudaEventDisableTiming);
    cudaEventCreateWithFlags(&evJoin, cudaEventDisableTiming);
    cudaEventRecord(evFork, 0);
    cudaStreamWaitEvent(s2, evFork, 0);
    k_gemm_mma<128, 128, 0><<<nbM, 256, 0, s2>>>(x, W1, NN);
    cudaEventRecord(evJoin, s2);

    // main stream: CSR build + normalization
    void* pcnt = nullptr;
    cudaGetSymbolAddress(&pcnt, g_cnt);
    cudaMemsetAsync(pcnt, 0, NN * sizeof(int), 0);
    k_hist<<<nbE, 256>>>(ei, E);
    k_scan_a<<<sb, 1024>>>();
    k_scan_b<<<sb, 1024>>>(sb);
    k_scatter<<<nbE, 256>>>(ei, E);

    // join, then layer 1 aggregation (applies dinv[s] per edge)
    cudaStreamWaitEvent(0, evJoin, 0);
    k_agg_h<128, 0><<<nbW, 256>>>(b1);

    // layer 2: 128 -> 64 (prescaled path)
    k_gemm_mma<128, 64, 1><<<nbM, 256>>>(nullptr, W2, NN);
    k_agg_h<64, 1><<<nbW, 256>>>(b2);

    // layer 3: 64 -> 32 + fused scoring
    k_gemm_mma<64, 32, 1><<<nbM, 256>>>(nullptr, W3, NN);
    k_agg3_score<<<nbW, 256>>>(b3, Wc);

    // edge scoring
    k_edgeout<<<nbE, 256>>>(ei, bc, out, E);
}

// round 9
// speedup vs baseline: 1.0711x; 1.0237x over previous
#include <cuda_runtime.h>
#include <cuda_fp16.h>
#include <stdint.h>

#define NN   100000
#define MAXE 1600000

// ---------------- device scratch (static; no allocations) ----------------
__device__ __align__(16) __half2 g_tf16[(size_t)NN * 64];  // fp16 t~ (all layers)
__device__ __align__(16) float   g_h[(size_t)NN * 128];    // layer outputs (fp32)
__device__ float g_dinv[NN];
__device__ float g_as[NN];
__device__ float g_bs[NN];
__device__ int   g_cnt[NN];
__device__ int   g_rowstart[NN + 1];
__device__ int   g_fill[NN];
__device__ int   g_bsum[256];
__device__ int   g_csr[MAXE];

// ---- per-block edge-index dtype probe ----
__device__ __forceinline__ int probe_is64(const int* __restrict__ ei,
                                          int* s_is64) {
    if (threadIdx.x < 32) {
        int nz = 0;
        for (int i = threadIdx.x; i < 64; i += 32)
            if (ei[2 * i + 1] != 0) nz = 1;
        unsigned m = __ballot_sync(0xFFFFFFFFu, nz);
        if (threadIdx.x == 0) *s_is64 = (m == 0) ? 1 : 0;
    }
    __syncthreads();
    return *s_is64;
}

// ---------------- graph preprocessing (4 edges/thread fast path) ----------------
__global__ void k_hist(const int* __restrict__ ei, int E) {
    __shared__ int s_is64;
    int is64 = probe_is64(ei, &s_is64);
    int e4 = (blockIdx.x * blockDim.x + threadIdx.x) * 4;
    if (e4 >= E) return;
    if (!is64 && e4 + 4 <= E) {
        int4 d = *(const int4*)(ei + E + e4);
        atomicAdd(&g_cnt[d.x], 1);
        atomicAdd(&g_cnt[d.y], 1);
        atomicAdd(&g_cnt[d.z], 1);
        atomicAdd(&g_cnt[d.w], 1);
    } else {
        for (int e = e4; e < e4 + 4 && e < E; e++) {
            int d = is64 ? ei[2 * (E + e)] : ei[E + e];
            atomicAdd(&g_cnt[d], 1);
        }
    }
}

// per-1024-chunk inclusive scan; writes rowstart[i+1] (pre-offset) + partials
__global__ void k_scan_a() {
    __shared__ int sh[1024];
    int i = blockIdx.x * 1024 + threadIdx.x;
    int v = (i < NN) ? g_cnt[i] : 0;
    sh[threadIdx.x] = v;
    __syncthreads();
    for (int off = 1; off < 1024; off <<= 1) {
        int t = (threadIdx.x >= off) ? sh[threadIdx.x - off] : 0;
        __syncthreads();
        sh[threadIdx.x] += t;
        __syncthreads();
    }
    if (i < NN) g_rowstart[i + 1] = sh[threadIdx.x];
    if (threadIdx.x == 1023) g_bsum[blockIdx.x] = sh[1023];
}

// add cross-block offsets (parallel warp-reduce of partials) + fill/dinv
__global__ void k_scan_b(int nblocks) {
    __shared__ int soff;
    __shared__ int wsum[4];
    if (threadIdx.x < 128) {
        int lane = threadIdx.x & 31, w = threadIdx.x >> 5;
        int v = (threadIdx.x < (int)blockIdx.x && threadIdx.x < nblocks)
                    ? g_bsum[threadIdx.x] : 0;
#pragma unroll
        for (int o = 16; o; o >>= 1) v += __shfl_xor_sync(0xFFFFFFFFu, v, o);
        if (lane == 0) wsum[w] = v;
    }
    __syncthreads();
    if (threadIdx.x == 0) soff = wsum[0] + wsum[1] + wsum[2] + wsum[3];
    __syncthreads();
    int off = soff;
    int i = blockIdx.x * 1024 + threadIdx.x;
    if (i < NN) {
        int prev = (threadIdx.x == 0) ? 0 : g_rowstart[i];  // pre-offset value
        g_fill[i] = prev + off;
        g_rowstart[i + 1] += off;
        g_dinv[i] = rsqrtf((float)g_cnt[i] + 1.0f);
        if (i == 0) g_rowstart[0] = 0;
    }
}

__global__ void k_scatter(const int* __restrict__ ei, int E) {
    __shared__ int s_is64;
    int is64 = probe_is64(ei, &s_is64);
    int e4 = (blockIdx.x * blockDim.x + threadIdx.x) * 4;
    if (e4 >= E) return;
    if (!is64 && e4 + 4 <= E) {
        int4 s = *(const int4*)(ei + e4);
        int4 d = *(const int4*)(ei + E + e4);
        g_csr[atomicAdd(&g_fill[d.x], 1)] = s.x;
        g_csr[atomicAdd(&g_fill[d.y], 1)] = s.y;
        g_csr[atomicAdd(&g_fill[d.z], 1)] = s.z;
        g_csr[atomicAdd(&g_fill[d.w], 1)] = s.w;
    } else {
        for (int e = e4; e < e4 + 4 && e < E; e++) {
            int s = is64 ? ei[2 * e] : ei[e];
            int d = is64 ? ei[2 * (E + e)] : ei[E + e];
            g_csr[atomicAdd(&g_fill[d], 1)] = s;
        }
    }
}

// ---- split-fp16 tensor GEMM (3-term, ~fp32 accurate): t~ = (X@W)[*dinv] ----
template <int K, int M, int PRESC>
__global__ void k_gemm_mma(const float* __restrict__ Xext,
                           const float* __restrict__ W, int n) {
    constexpr int BK  = 32;
    constexpr int STG = K / BK;
    constexpr int AP  = BK + 8;
    constexpr int WC  = (M >= 128) ? 2 : 1;
    constexpr int WR  = 8 / WC;
    constexpr int WROWS = 128 / WR;
    constexpr int WCOLS = M / WC;
    constexpr int MT  = WROWS / 16;
    constexpr int NT  = WCOLS / 8;

    __shared__ __align__(16) __half Ah[128 * AP];
    __shared__ __align__(16) __half Al[128 * AP];
    __shared__ __align__(16) __half Bh[M * AP];
    __shared__ __align__(16) __half Bl[M * AP];

    const float* __restrict__ X = Xext ? Xext : g_h;
    int t    = threadIdx.x;
    int warp = t >> 5, lane = t & 31;
    int g    = lane >> 2, tg = lane & 3;
    int wm   = (warp % WR) * WROWS;
    int wn   = (warp / WR) * WCOLS;
    int base = blockIdx.x * 128;

    float acc[MT][NT][4];
#pragma unroll
    for (int mt = 0; mt < MT; mt++)
#pragma unroll
        for (int nt = 0; nt < NT; nt++)
#pragma unroll
            for (int j = 0; j < 4; j++) acc[mt][nt][j] = 0.f;

    for (int s = 0; s < STG; s++) {
        int k0 = s * BK;
#pragma unroll
        for (int j = 0; j < 4; j++) {
            int idx = t + j * 256;
            int r = idx >> 3, c4 = idx & 7;
            float4 v = make_float4(0.f, 0.f, 0.f, 0.f);
            if (base + r < n)
                v = *(const float4*)(X + (size_t)(base + r) * K + k0 + c4 * 4);
            __half hx = __float2half_rn(v.x), hy = __float2half_rn(v.y);
            __half hz = __float2half_rn(v.z), hw = __float2half_rn(v.w);
            __half2 h0 = __halves2half2(hx, hy);
            __half2 h1 = __halves2half2(hz, hw);
            __half2 l0 = __floats2half2_rn(v.x - __half2float(hx), v.y - __half2float(hy));
            __half2 l1 = __floats2half2_rn(v.z - __half2float(hz), v.w - __half2float(hw));
            uint2 uh, ul;
            uh.x = *(unsigned*)&h0; uh.y = *(unsigned*)&h1;
            ul.x = *(unsigned*)&l0; ul.y = *(unsigned*)&l1;
            *(uint2*)&Ah[r * AP + c4 * 4] = uh;
            *(uint2*)&Al[r * AP + c4 * 4] = ul;
        }
        constexpr int WE = (BK * M) / 256;
#pragma unroll
        for (int j = 0; j < WE; j++) {
            int idx = t + j * 256;
            int k = idx / M, m = idx % M;
            float w = W[(size_t)(k0 + k) * M + m];
            __half wh = __float2half_rn(w);
            Bh[m * AP + k] = wh;
            Bl[m * AP + k] = __float2half_rn(w - __half2float(wh));
        }
        __syncthreads();

#pragma unroll
        for (int kk = 0; kk < BK; kk += 16) {
            unsigned ah[MT][4], al[MT][4], bh[NT][2], bl[NT][2];
#pragma unroll
            for (int mt = 0; mt < MT; mt++) {
                int off = (wm + mt * 16 + g) * AP + kk + tg * 2;
                ah[mt][0] = *(const unsigned*)&Ah[off];
                ah[mt][1] = *(const unsigned*)&Ah[off + 8 * AP];
                ah[mt][2] = *(const unsigned*)&Ah[off + 8];
                ah[mt][3] = *(const unsigned*)&Ah[off + 8 * AP + 8];
                al[mt][0] = *(const unsigned*)&Al[off];
                al[mt][1] = *(const unsigned*)&Al[off + 8 * AP];
                al[mt][2] = *(const unsigned*)&Al[off + 8];
                al[mt][3] = *(const unsigned*)&Al[off + 8 * AP + 8];
            }
#pragma unroll
            for (int nt = 0; nt < NT; nt++) {
                int off = (wn + nt * 8 + g) * AP + kk + tg * 2;
                bh[nt][0] = *(const unsigned*)&Bh[off];
                bh[nt][1] = *(const unsigned*)&Bh[off + 8];
                bl[nt][0] = *(const unsigned*)&Bl[off];
                bl[nt][1] = *(const unsigned*)&Bl[off + 8];
            }
#define MMA(AC, A0, A1, A2, A3, B0, B1)                                       \
    asm volatile(                                                             \
        "mma.sync.aligned.m16n8k16.row.col.f32.f16.f16.f32 "                  \
        "{%0,%1,%2,%3},{%4,%5,%6,%7},{%8,%9},{%0,%1,%2,%3};"                  \
        : "+f"(AC[0]), "+f"(AC[1]), "+f"(AC[2]), "+f"(AC[3])                  \
        : "r"(A0), "r"(A1), "r"(A2), "r"(A3), "r"(B0), "r"(B1))
#pragma unroll
            for (int mt = 0; mt < MT; mt++)
#pragma unroll
                for (int nt = 0; nt < NT; nt++) {
                    MMA(acc[mt][nt], ah[mt][0], ah[mt][1], ah[mt][2], ah[mt][3],
                        bh[nt][0], bh[nt][1]);
                    MMA(acc[mt][nt], ah[mt][0], ah[mt][1], ah[mt][2], ah[mt][3],
                        bl[nt][0], bl[nt][1]);
                    MMA(acc[mt][nt], al[mt][0], al[mt][1], al[mt][2], al[mt][3],
                        bh[nt][0], bh[nt][1]);
                }
#undef MMA
        }
        __syncthreads();
    }

#pragma unroll
    for (int mt = 0; mt < MT; mt++) {
        int r0 = base + wm + mt * 16 + g;
        int r1 = r0 + 8;
        float s0 = PRESC ? ((r0 < n) ? g_dinv[r0] : 0.f) : 1.f;
        float s1 = PRESC ? ((r1 < n) ? g_dinv[r1] : 0.f) : 1.f;
#pragma unroll
        for (int nt = 0; nt < NT; nt++) {
            int c = wn + nt * 8 + tg * 2;
            if (r0 < n)
                g_tf16[(size_t)r0 * (M / 2) + (c >> 1)] =
                    __floats2half2_rn(acc[mt][nt][0] * s0, acc[mt][nt][1] * s0);
            if (r1 < n)
                g_tf16[(size_t)r1 * (M / 2) + (c >> 1)] =
                    __floats2half2_rn(acc[mt][nt][2] * s1, acc[mt][nt][3] * s1);
        }
    }
}

// ---------- aggregation over fp16 rows. SCALED: t~ already has dinv[s] ----------
template <int M, int SCALED>
__global__ void k_agg_h(const float* __restrict__ bias) {
    constexpr int V2 = M / 64;
    int gw   = (blockIdx.x * blockDim.x + threadIdx.x) >> 5;
    int lane = threadIdx.x & 31;
    if (gw >= NN) return;

    float dd = g_dinv[gw];
    int rs = g_rowstart[gw];
    int re = g_rowstart[gw + 1];

    float acc[2 * V2];
#pragma unroll
    for (int v = 0; v < 2 * V2; v++) acc[v] = 0.f;

    int e = rs;
    for (; e + 4 <= re; e += 4) {       // unroll x4 for row-load MLP
        int s0 = __ldg(&g_csr[e]),     s1 = __ldg(&g_csr[e + 1]);
        int s2 = __ldg(&g_csr[e + 2]), s3 = __ldg(&g_csr[e + 3]);
        float w0 = SCALED ? 1.f : __ldg(&g_dinv[s0]);
        float w1 = SCALED ? 1.f : __ldg(&g_dinv[s1]);
        float w2 = SCALED ? 1.f : __ldg(&g_dinv[s2]);
        float w3 = SCALED ? 1.f : __ldg(&g_dinv[s3]);
        const __half2* r0 = g_tf16 + (size_t)s0 * (M / 2) + lane * V2;
        const __half2* r1 = g_tf16 + (size_t)s1 * (M / 2) + lane * V2;
        const __half2* r2 = g_tf16 + (size_t)s2 * (M / 2) + lane * V2;
        const __half2* r3 = g_tf16 + (size_t)s3 * (M / 2) + lane * V2;
        if (V2 == 2) {
            float2 a0 = *(const float2*)r0, a1 = *(const float2*)r1;
            float2 a2 = *(const float2*)r2, a3 = *(const float2*)r3;
            float2 f;
            f = __half22float2(*(__half2*)&a0.x); acc[0] += f.x * w0; acc[1] += f.y * w0;
            f = __half22float2(*(__half2*)&a0.y); acc[2] += f.x * w0; acc[3] += f.y * w0;
            f = __half22float2(*(__half2*)&a1.x); acc[0] += f.x * w1; acc[1] += f.y * w1;
            f = __half22float2(*(__half2*)&a1.y); acc[2] += f.x * w1; acc[3] += f.y * w1;
            f = __half22float2(*(__half2*)&a2.x); acc[0] += f.x * w2; acc[1] += f.y * w2;
            f = __half22float2(*(__half2*)&a2.y); acc[2] += f.x * w2; acc[3] += f.y * w2;
            f = __half22float2(*(__half2*)&a3.x); acc[0] += f.x * w3; acc[1] += f.y * w3;
            f = __half22float2(*(__half2*)&a3.y); acc[2] += f.x * w3; acc[3] += f.y * w3;
        } else {
            float2 f0 = __half22float2(r0[0]), f1 = __half22float2(r1[0]);
            float2 f2 = __half22float2(r2[0]), f3 = __half22float2(r3[0]);
            acc[0] += f0.x * w0 + f1.x * w1 + f2.x * w2 + f3.x * w3;
            acc[1] += f0.y * w0 + f1.y * w1 + f2.y * w2 + f3.y * w3;
        }
    }
    for (; e < re; e++) {
        int s = __ldg(&g_csr[e]);
        float w = SCALED ? 1.f : __ldg(&g_dinv[s]);
        const __half2* row = g_tf16 + (size_t)s * (M / 2) + lane * V2;
#pragma unroll
        for (int v = 0; v < V2; v++) {
            float2 f = __half22float2(row[v]);
            acc[2 * v] += f.x * w; acc[2 * v + 1] += f.y * w;
        }
    }
    {   // self loop
        float w = SCALED ? 1.f : dd;
        const __half2* row = g_tf16 + (size_t)gw * (M / 2) + lane * V2;
#pragma unroll
        for (int v = 0; v < V2; v++) {
            float2 f = __half22float2(row[v]);
            acc[2 * v] += f.x * w; acc[2 * v + 1] += f.y * w;
        }
    }
#pragma unroll
    for (int v = 0; v < 2 * V2; v++) {
        float o = acc[v] * dd + bias[lane * 2 * V2 + v];
        g_h[(size_t)gw * M + lane * 2 * V2 + v] = fmaxf(o, 0.f);
    }
}

// ---- layer-3 agg (fp16, 2 edges/warp via half-warps) fused with scoring ----
__global__ void k_agg3_score(const float* __restrict__ bias,
                             const float* __restrict__ Wc) {
    int gw   = (blockIdx.x * blockDim.x + threadIdx.x) >> 5;
    int lane = threadIdx.x & 31;
    if (gw >= NN) return;

    int half = lane >> 4;
    int hl   = lane & 15;

    float dd = g_dinv[gw];
    int rs = g_rowstart[gw];
    int re = g_rowstart[gw + 1];

    float a0 = 0.f, a1 = 0.f;
    for (int e = rs + half; e < re; e += 2) {
        int s = __ldg(&g_csr[e]);
        float2 f = __half22float2(g_tf16[(size_t)s * 16 + hl]);
        a0 += f.x; a1 += f.y;
    }
    a0 += __shfl_down_sync(0xFFFFFFFFu, a0, 16);
    a1 += __shfl_down_sync(0xFFFFFFFFu, a1, 16);

    float2 fs = __half22float2(g_tf16[(size_t)gw * 16 + hl]);
    a0 += fs.x; a1 += fs.y;
    float o0 = fmaxf(a0 * dd + bias[2 * hl], 0.f);
    float o1 = fmaxf(a1 * dd + bias[2 * hl + 1], 0.f);
    float p = o0 * Wc[2 * hl] + o1 * Wc[2 * hl + 1];
    float q = o0 * Wc[32 + 2 * hl] + o1 * Wc[32 + 2 * hl + 1];
#pragma unroll
    for (int off = 8; off; off >>= 1) {
        p += __shfl_xor_sync(0xFFFFFFFFu, p, off);
        q += __shfl_xor_sync(0xFFFFFFFFu, q, off);
    }
    if (lane == 0) { g_as[gw] = p; g_bs[gw] = q; }
}

__global__ void k_edgeout(const int* __restrict__ ei,
                          const float* __restrict__ bc,
                          float* __restrict__ out, int E) {
    __shared__ int s_is64;
    int is64 = probe_is64(ei, &s_is64);
    float b = bc[0];
    int e4 = (blockIdx.x * blockDim.x + threadIdx.x) * 4;
    if (e4 >= E) return;
    if (!is64 && e4 + 4 <= E) {
        int4 s = *(const int4*)(ei + e4);
        int4 d = *(const int4*)(ei + E + e4);
        float4 o;
        o.x = __ldg(&g_as[s.x]) + __ldg(&g_bs[d.x]) + b;
        o.y = __ldg(&g_as[s.y]) + __ldg(&g_bs[d.y]) + b;
        o.z = __ldg(&g_as[s.z]) + __ldg(&g_bs[d.z]) + b;
        o.w = __ldg(&g_as[s.w]) + __ldg(&g_bs[d.w]) + b;
        *(float4*)(out + e4) = o;
    } else {
        for (int e = e4; e < e4 + 4 && e < E; e++) {
            int s = is64 ? ei[2 * e] : ei[e];
            int d = is64 ? ei[2 * (E + e)] : ei[E + e];
            out[e] = g_as[s] + g_bs[d] + b;
        }
    }
}

// ---------------- launch ----------------
extern "C" void kernel_launch(void* const* d_in, const int* in_sizes, int n_in,
                              void* d_out, int out_size) {
    const float* x   = (const float*)d_in[0];
    const int*   ei  = (const int*)d_in[1];
    const float* W1  = (const float*)d_in[2];
    const float* b1  = (const float*)d_in[3];
    const float* W2  = (const float*)d_in[4];
    const float* b2  = (const float*)d_in[5];
    const float* W3  = (const float*)d_in[6];
    const float* b3  = (const float*)d_in[7];
    const float* Wc  = (const float*)d_in[8];
    const float* bc  = (const float*)d_in[9];
    float*       out = (float*)d_out;

    int E = in_sizes[1] / 2;

    int nbE4 = ((E + 3) / 4 + 255) / 256;  // 4 edges per thread
    int sb   = (NN + 1023) / 1024;
    int nbW  = (NN * 32 + 255) / 256;      // warp-per-node kernels
    int nbM  = (NN + 127) / 128;           // mma GEMM blocks

    // fork: layer-1 GEMM (no prescale) overlaps the CSR build
    cudaStream_t s2;
    cudaEvent_t evFork, evJoin;
    cudaStreamCreateWithFlags(&s2, cudaStreamNonBlocking);
    cudaEventCreateWithFlags(&evFork, cudaEventDisableTiming);
    cudaEventCreateWithFlags(&evJoin, cudaEventDisableTiming);
    cudaEventRecord(evFork, 0);
    cudaStreamWaitEvent(s2, evFork, 0);
    k_gemm_mma<128, 128, 0><<<nbM, 256, 0, s2>>>(x, W1, NN);
    cudaEventRecord(evJoin, s2);

    // main stream: CSR build + normalization
    void* pcnt = nullptr;
    cudaGetSymbolAddress(&pcnt, g_cnt);
    cudaMemsetAsync(pcnt, 0, NN * sizeof(int), 0);
    k_hist<<<nbE4, 256>>>(ei, E);
    k_scan_a<<<sb, 1024>>>();
    k_scan_b<<<sb, 1024>>>(sb);
    k_scatter<<<nbE4, 256>>>(ei, E);

    // join, then layer 1 aggregation (applies dinv[s] per edge)
    cudaStreamWaitEvent(0, evJoin, 0);
    k_agg_h<128, 0><<<nbW, 256>>>(b1);

    // layer 2: 128 -> 64 (prescaled path)
    k_gemm_mma<128, 64, 1><<<nbM, 256>>>(nullptr, W2, NN);
    k_agg_h<64, 1><<<nbW, 256>>>(b2);

    // layer 3: 64 -> 32 + fused scoring
    k_gemm_mma<64, 32, 1><<<nbM, 256>>>(nullptr, W3, NN);
    k_agg3_score<<<nbW, 256>>>(b3, Wc);

    // edge scoring
    k_edgeout<<<nbE4, 256>>>(ei, bc, out, E);
}

// round 10
// speedup vs baseline: 1.1175x; 1.0433x over previous
#include <cuda_runtime.h>
#include <cuda_fp16.h>
#include <stdint.h>

#define NN   100000
#define MAXE 1600000

// ---------------- device scratch (static; no allocations) ----------------
__device__ __align__(16) __half2 g_tf16[(size_t)NN * 64];  // fp16 t~ (pre-agg)
__device__ __align__(16) __half2 g_hh[(size_t)NN * 64];    // fp16 layer outputs
__device__ float g_dinv[NN];
__device__ float g_as[NN];
__device__ float g_bs[NN];
__device__ int   g_cnt[NN];
__device__ int   g_rowstart[NN + 1];
__device__ int   g_fill[NN];
__device__ int   g_bsum[256];
__device__ int   g_csr[MAXE];

// ---- per-block edge-index dtype probe ----
__device__ __forceinline__ int probe_is64(const int* __restrict__ ei,
                                          int* s_is64) {
    if (threadIdx.x < 32) {
        int nz = 0;
        for (int i = threadIdx.x; i < 64; i += 32)
            if (ei[2 * i + 1] != 0) nz = 1;
        unsigned m = __ballot_sync(0xFFFFFFFFu, nz);
        if (threadIdx.x == 0) *s_is64 = (m == 0) ? 1 : 0;
    }
    __syncthreads();
    return *s_is64;
}

// ---------------- graph preprocessing (4 edges/thread fast path) ----------------
__global__ void k_hist(const int* __restrict__ ei, int E) {
    __shared__ int s_is64;
    int is64 = probe_is64(ei, &s_is64);
    int e4 = (blockIdx.x * blockDim.x + threadIdx.x) * 4;
    if (e4 >= E) return;
    if (!is64 && e4 + 4 <= E) {
        int4 d = *(const int4*)(ei + E + e4);
        atomicAdd(&g_cnt[d.x], 1);
        atomicAdd(&g_cnt[d.y], 1);
        atomicAdd(&g_cnt[d.z], 1);
        atomicAdd(&g_cnt[d.w], 1);
    } else {
        for (int e = e4; e < e4 + 4 && e < E; e++) {
            int d = is64 ? ei[2 * (E + e)] : ei[E + e];
            atomicAdd(&g_cnt[d], 1);
        }
    }
}

__global__ void k_scan_a() {
    __shared__ int sh[1024];
    int i = blockIdx.x * 1024 + threadIdx.x;
    int v = (i < NN) ? g_cnt[i] : 0;
    sh[threadIdx.x] = v;
    __syncthreads();
    for (int off = 1; off < 1024; off <<= 1) {
        int t = (threadIdx.x >= off) ? sh[threadIdx.x - off] : 0;
        __syncthreads();
        sh[threadIdx.x] += t;
        __syncthreads();
    }
    if (i < NN) g_rowstart[i + 1] = sh[threadIdx.x];
    if (threadIdx.x == 1023) g_bsum[blockIdx.x] = sh[1023];
}

__global__ void k_scan_b(int nblocks) {
    __shared__ int soff;
    __shared__ int wsum[4];
    if (threadIdx.x < 128) {
        int lane = threadIdx.x & 31, w = threadIdx.x >> 5;
        int v = (threadIdx.x < (int)blockIdx.x && threadIdx.x < nblocks)
                    ? g_bsum[threadIdx.x] : 0;
#pragma unroll
        for (int o = 16; o; o >>= 1) v += __shfl_xor_sync(0xFFFFFFFFu, v, o);
        if (lane == 0) wsum[w] = v;
    }
    __syncthreads();
    if (threadIdx.x == 0) soff = wsum[0] + wsum[1] + wsum[2] + wsum[3];
    __syncthreads();
    int off = soff;
    int i = blockIdx.x * 1024 + threadIdx.x;
    if (i < NN) {
        int prev = (threadIdx.x == 0) ? 0 : g_rowstart[i];
        g_fill[i] = prev + off;
        g_rowstart[i + 1] += off;
        g_dinv[i] = rsqrtf((float)g_cnt[i] + 1.0f);
        if (i == 0) g_rowstart[0] = 0;
    }
}

__global__ void k_scatter(const int* __restrict__ ei, int E) {
    __shared__ int s_is64;
    int is64 = probe_is64(ei, &s_is64);
    int e4 = (blockIdx.x * blockDim.x + threadIdx.x) * 4;
    if (e4 >= E) return;
    if (!is64 && e4 + 4 <= E) {
        int4 s = *(const int4*)(ei + e4);
        int4 d = *(const int4*)(ei + E + e4);
        g_csr[atomicAdd(&g_fill[d.x], 1)] = s.x;
        g_csr[atomicAdd(&g_fill[d.y], 1)] = s.y;
        g_csr[atomicAdd(&g_fill[d.z], 1)] = s.z;
        g_csr[atomicAdd(&g_fill[d.w], 1)] = s.w;
    } else {
        for (int e = e4; e < e4 + 4 && e < E; e++) {
            int s = is64 ? ei[2 * e] : ei[e];
            int d = is64 ? ei[2 * (E + e)] : ei[E + e];
            g_csr[atomicAdd(&g_fill[d], 1)] = s;
        }
    }
}

// ---- split-fp16 tensor GEMM: t~ = (X@W)[*dinv], fp16 out ----
// X16: A is fp16 (g_hh) -> Al==0, only 2 mma terms. Else A fp32 (Xext), 3 terms.
template <int K, int M, int PRESC, int X16>
__global__ void k_gemm_mma(const float* __restrict__ Xext,
                           const float* __restrict__ W, int n) {
    constexpr int BK  = 32;
    constexpr int STG = K / BK;
    constexpr int AP  = BK + 8;
    constexpr int WC  = (M >= 128) ? 2 : 1;
    constexpr int WR  = 8 / WC;
    constexpr int WROWS = 128 / WR;
    constexpr int WCOLS = M / WC;
    constexpr int MT  = WROWS / 16;
    constexpr int NT  = WCOLS / 8;

    __shared__ __align__(16) __half Ah[128 * AP];
    __shared__ __align__(16) __half Al[128 * AP];
    __shared__ __align__(16) __half Bh[M * AP];
    __shared__ __align__(16) __half Bl[M * AP];

    int t    = threadIdx.x;
    int warp = t >> 5, lane = t & 31;
    int g    = lane >> 2, tg = lane & 3;
    int wm   = (warp % WR) * WROWS;
    int wn   = (warp / WR) * WCOLS;
    int base = blockIdx.x * 128;

    float acc[MT][NT][4];
#pragma unroll
    for (int mt = 0; mt < MT; mt++)
#pragma unroll
        for (int nt = 0; nt < NT; nt++)
#pragma unroll
            for (int j = 0; j < 4; j++) acc[mt][nt][j] = 0.f;

    for (int s = 0; s < STG; s++) {
        int k0 = s * BK;
#pragma unroll
        for (int j = 0; j < 4; j++) {
            int idx = t + j * 256;
            int r = idx >> 3, c4 = idx & 7;
            if (X16) {
                uint2 u = make_uint2(0u, 0u);
                if (base + r < n)
                    u = *(const uint2*)(g_hh + (size_t)(base + r) * (K / 2) +
                                        k0 / 2 + c4 * 2);
                *(uint2*)&Ah[r * AP + c4 * 4] = u;
            } else {
                float4 v = make_float4(0.f, 0.f, 0.f, 0.f);
                if (base + r < n)
                    v = *(const float4*)(Xext + (size_t)(base + r) * K + k0 + c4 * 4);
                __half hx = __float2half_rn(v.x), hy = __float2half_rn(v.y);
                __half hz = __float2half_rn(v.z), hw = __float2half_rn(v.w);
                __half2 h0 = __halves2half2(hx, hy);
                __half2 h1 = __halves2half2(hz, hw);
                __half2 l0 = __floats2half2_rn(v.x - __half2float(hx), v.y - __half2float(hy));
                __half2 l1 = __floats2half2_rn(v.z - __half2float(hz), v.w - __half2float(hw));
                uint2 uh, ul;
                uh.x = *(unsigned*)&h0; uh.y = *(unsigned*)&h1;
                ul.x = *(unsigned*)&l0; ul.y = *(unsigned*)&l1;
                *(uint2*)&Ah[r * AP + c4 * 4] = uh;
                *(uint2*)&Al[r * AP + c4 * 4] = ul;
            }
        }
        constexpr int WE = (BK * M) / 256;
#pragma unroll
        for (int j = 0; j < WE; j++) {
            int idx = t + j * 256;
            int k = idx / M, m = idx % M;
            float w = W[(size_t)(k0 + k) * M + m];
            __half wh = __float2half_rn(w);
            Bh[m * AP + k] = wh;
            Bl[m * AP + k] = __float2half_rn(w - __half2float(wh));
        }
        __syncthreads();

#pragma unroll
        for (int kk = 0; kk < BK; kk += 16) {
            unsigned ah[MT][4], al[MT][4], bh[NT][2], bl[NT][2];
#pragma unroll
            for (int mt = 0; mt < MT; mt++) {
                int off = (wm + mt * 16 + g) * AP + kk + tg * 2;
                ah[mt][0] = *(const unsigned*)&Ah[off];
                ah[mt][1] = *(const unsigned*)&Ah[off + 8 * AP];
                ah[mt][2] = *(const unsigned*)&Ah[off + 8];
                ah[mt][3] = *(const unsigned*)&Ah[off + 8 * AP + 8];
                if (!X16) {
                    al[mt][0] = *(const unsigned*)&Al[off];
                    al[mt][1] = *(const unsigned*)&Al[off + 8 * AP];
                    al[mt][2] = *(const unsigned*)&Al[off + 8];
                    al[mt][3] = *(const unsigned*)&Al[off + 8 * AP + 8];
                }
            }
#pragma unroll
            for (int nt = 0; nt < NT; nt++) {
                int off = (wn + nt * 8 + g) * AP + kk + tg * 2;
                bh[nt][0] = *(const unsigned*)&Bh[off];
                bh[nt][1] = *(const unsigned*)&Bh[off + 8];
                bl[nt][0] = *(const unsigned*)&Bl[off];
                bl[nt][1] = *(const unsigned*)&Bl[off + 8];
            }
#define MMA(AC, A0, A1, A2, A3, B0, B1)                                       \
    asm volatile(                                                             \
        "mma.sync.aligned.m16n8k16.row.col.f32.f16.f16.f32 "                  \
        "{%0,%1,%2,%3},{%4,%5,%6,%7},{%8,%9},{%0,%1,%2,%3};"                  \
        : "+f"(AC[0]), "+f"(AC[1]), "+f"(AC[2]), "+f"(AC[3])                  \
        : "r"(A0), "r"(A1), "r"(A2), "r"(A3), "r"(B0), "r"(B1))
#pragma unroll
            for (int mt = 0; mt < MT; mt++)
#pragma unroll
                for (int nt = 0; nt < NT; nt++) {
                    MMA(acc[mt][nt], ah[mt][0], ah[mt][1], ah[mt][2], ah[mt][3],
                        bh[nt][0], bh[nt][1]);
                    MMA(acc[mt][nt], ah[mt][0], ah[mt][1], ah[mt][2], ah[mt][3],
                        bl[nt][0], bl[nt][1]);
                    if (!X16)
                        MMA(acc[mt][nt], al[mt][0], al[mt][1], al[mt][2], al[mt][3],
                            bh[nt][0], bh[nt][1]);
                }
#undef MMA
        }
        __syncthreads();
    }

#pragma unroll
    for (int mt = 0; mt < MT; mt++) {
        int r0 = base + wm + mt * 16 + g;
        int r1 = r0 + 8;
        float s0 = PRESC ? ((r0 < n) ? g_dinv[r0] : 0.f) : 1.f;
        float s1 = PRESC ? ((r1 < n) ? g_dinv[r1] : 0.f) : 1.f;
#pragma unroll
        for (int nt = 0; nt < NT; nt++) {
            int c = wn + nt * 8 + tg * 2;
            if (r0 < n)
                g_tf16[(size_t)r0 * (M / 2) + (c >> 1)] =
                    __floats2half2_rn(acc[mt][nt][0] * s0, acc[mt][nt][1] * s0);
            if (r1 < n)
                g_tf16[(size_t)r1 * (M / 2) + (c >> 1)] =
                    __floats2half2_rn(acc[mt][nt][2] * s1, acc[mt][nt][3] * s1);
        }
    }
}

// ---------- aggregation over fp16 t~ rows; writes fp16 h ----------
// SCALED: t~ already carries dinv[s].
template <int M, int SCALED>
__global__ void k_agg_h(const float* __restrict__ bias) {
    constexpr int V2 = M / 64;
    int gw   = (blockIdx.x * blockDim.x + threadIdx.x) >> 5;
    int lane = threadIdx.x & 31;
    if (gw >= NN) return;

    float dd = g_dinv[gw];
    int rs = g_rowstart[gw];
    int re = g_rowstart[gw + 1];

    float acc[2 * V2];
#pragma unroll
    for (int v = 0; v < 2 * V2; v++) acc[v] = 0.f;

    int e = rs;
    for (; e + 4 <= re; e += 4) {
        int s0 = __ldg(&g_csr[e]),     s1 = __ldg(&g_csr[e + 1]);
        int s2 = __ldg(&g_csr[e + 2]), s3 = __ldg(&g_csr[e + 3]);
        float w0 = SCALED ? 1.f : __ldg(&g_dinv[s0]);
        float w1 = SCALED ? 1.f : __ldg(&g_dinv[s1]);
        float w2 = SCALED ? 1.f : __ldg(&g_dinv[s2]);
        float w3 = SCALED ? 1.f : __ldg(&g_dinv[s3]);
        const __half2* r0 = g_tf16 + (size_t)s0 * (M / 2) + lane * V2;
        const __half2* r1 = g_tf16 + (size_t)s1 * (M / 2) + lane * V2;
        const __half2* r2 = g_tf16 + (size_t)s2 * (M / 2) + lane * V2;
        const __half2* r3 = g_tf16 + (size_t)s3 * (M / 2) + lane * V2;
        if (V2 == 2) {
            float2 a0 = *(const float2*)r0, a1 = *(const float2*)r1;
            float2 a2 = *(const float2*)r2, a3 = *(const float2*)r3;
            float2 f;
            f = __half22float2(*(__half2*)&a0.x); acc[0] += f.x * w0; acc[1] += f.y * w0;
            f = __half22float2(*(__half2*)&a0.y); acc[2] += f.x * w0; acc[3] += f.y * w0;
            f = __half22float2(*(__half2*)&a1.x); acc[0] += f.x * w1; acc[1] += f.y * w1;
            f = __half22float2(*(__half2*)&a1.y); acc[2] += f.x * w1; acc[3] += f.y * w1;
            f = __half22float2(*(__half2*)&a2.x); acc[0] += f.x * w2; acc[1] += f.y * w2;
            f = __half22float2(*(__half2*)&a2.y); acc[2] += f.x * w2; acc[3] += f.y * w2;
            f = __half22float2(*(__half2*)&a3.x); acc[0] += f.x * w3; acc[1] += f.y * w3;
            f = __half22float2(*(__half2*)&a3.y); acc[2] += f.x * w3; acc[3] += f.y * w3;
        } else {
            float2 f0 = __half22float2(r0[0]), f1 = __half22float2(r1[0]);
            float2 f2 = __half22float2(r2[0]), f3 = __half22float2(r3[0]);
            acc[0] += f0.x * w0 + f1.x * w1 + f2.x * w2 + f3.x * w3;
            acc[1] += f0.y * w0 + f1.y * w1 + f2.y * w2 + f3.y * w3;
        }
    }
    for (; e < re; e++) {
        int s = __ldg(&g_csr[e]);
        float w = SCALED ? 1.f : __ldg(&g_dinv[s]);
        const __half2* row = g_tf16 + (size_t)s * (M / 2) + lane * V2;
#pragma unroll
        for (int v = 0; v < V2; v++) {
            float2 f = __half22float2(row[v]);
            acc[2 * v] += f.x * w; acc[2 * v + 1] += f.y * w;
        }
    }
    {   // self loop
        float w = SCALED ? 1.f : dd;
        const __half2* row = g_tf16 + (size_t)gw * (M / 2) + lane * V2;
#pragma unroll
        for (int v = 0; v < V2; v++) {
            float2 f = __half22float2(row[v]);
            acc[2 * v] += f.x * w; acc[2 * v + 1] += f.y * w;
        }
    }
#pragma unroll
    for (int v = 0; v < V2; v++) {
        float o0 = fmaxf(acc[2 * v] * dd + bias[lane * 2 * V2 + 2 * v], 0.f);
        float o1 = fmaxf(acc[2 * v + 1] * dd + bias[lane * 2 * V2 + 2 * v + 1], 0.f);
        g_hh[(size_t)gw * (M / 2) + lane * V2 + v] = __floats2half2_rn(o0, o1);
    }
}

// ---- layer-3 agg (fp16, 2 edges/warp via half-warps) fused with scoring ----
__global__ void k_agg3_score(const float* __restrict__ bias,
                             const float* __restrict__ Wc) {
    int gw   = (blockIdx.x * blockDim.x + threadIdx.x) >> 5;
    int lane = threadIdx.x & 31;
    if (gw >= NN) return;

    int half = lane >> 4;
    int hl   = lane & 15;

    float dd = g_dinv[gw];
    int rs = g_rowstart[gw];
    int re = g_rowstart[gw + 1];

    float a0 = 0.f, a1 = 0.f;
    for (int e = rs + half; e < re; e += 2) {
        int s = __ldg(&g_csr[e]);
        float2 f = __half22float2(g_tf16[(size_t)s * 16 + hl]);
        a0 += f.x; a1 += f.y;
    }
    a0 += __shfl_down_sync(0xFFFFFFFFu, a0, 16);
    a1 += __shfl_down_sync(0xFFFFFFFFu, a1, 16);

    float2 fs = __half22float2(g_tf16[(size_t)gw * 16 + hl]);
    a0 += fs.x; a1 += fs.y;
    float o0 = fmaxf(a0 * dd + bias[2 * hl], 0.f);
    float o1 = fmaxf(a1 * dd + bias[2 * hl + 1], 0.f);
    float p = o0 * Wc[2 * hl] + o1 * Wc[2 * hl + 1];
    float q = o0 * Wc[32 + 2 * hl] + o1 * Wc[32 + 2 * hl + 1];
#pragma unroll
    for (int off = 8; off; off >>= 1) {
        p += __shfl_xor_sync(0xFFFFFFFFu, p, off);
        q += __shfl_xor_sync(0xFFFFFFFFu, q, off);
    }
    if (lane == 0) { g_as[gw] = p; g_bs[gw] = q; }
}

__global__ void k_edgeout(const int* __restrict__ ei,
                          const float* __restrict__ bc,
                          float* __restrict__ out, int E) {
    __shared__ int s_is64;
    int is64 = probe_is64(ei, &s_is64);
    float b = bc[0];
    int e4 = (blockIdx.x * blockDim.x + threadIdx.x) * 4;
    if (e4 >= E) return;
    if (!is64 && e4 + 4 <= E) {
        int4 s = *(const int4*)(ei + e4);
        int4 d = *(const int4*)(ei + E + e4);
        float4 o;
        o.x = __ldg(&g_as[s.x]) + __ldg(&g_bs[d.x]) + b;
        o.y = __ldg(&g_as[s.y]) + __ldg(&g_bs[d.y]) + b;
        o.z = __ldg(&g_as[s.z]) + __ldg(&g_bs[d.z]) + b;
        o.w = __ldg(&g_as[s.w]) + __ldg(&g_bs[d.w]) + b;
        *(float4*)(out + e4) = o;
    } else {
        for (int e = e4; e < e4 + 4 && e < E; e++) {
            int s = is64 ? ei[2 * e] : ei[e];
            int d = is64 ? ei[2 * (E + e)] : ei[E + e];
            out[e] = g_as[s] + g_bs[d] + b;
        }
    }
}

// ---------------- launch ----------------
extern "C" void kernel_launch(void* const* d_in, const int* in_sizes, int n_in,
                              void* d_out, int out_size) {
    const float* x   = (const float*)d_in[0];
    const int*   ei  = (const int*)d_in[1];
    const float* W1  = (const float*)d_in[2];
    const float* b1  = (const float*)d_in[3];
    const float* W2  = (const float*)d_in[4];
    const float* b2  = (const float*)d_in[5];
    const float* W3  = (const float*)d_in[6];
    const float* b3  = (const float*)d_in[7];
    const float* Wc  = (const float*)d_in[8];
    const float* bc  = (const float*)d_in[9];
    float*       out = (float*)d_out;

    int E = in_sizes[1] / 2;

    int nbE4 = ((E + 3) / 4 + 255) / 256;
    int sb   = (NN + 1023) / 1024;
    int nbW  = (NN * 32 + 255) / 256;
    int nbM  = (NN + 127) / 128;

    // fork: layer-1 GEMM (fp32 A, no prescale) overlaps the CSR build
    cudaStream_t s2;
    cudaEvent_t evFork, evJoin;
    cudaStreamCreateWithFlags(&s2, cudaStreamNonBlocking);
    cudaEventCreateWithFlags(&evFork, cudaEventDisableTiming);
    cudaEventCreateWithFlags(&evJoin, cudaEventDisableTiming);
    cudaEventRecord(evFork, 0);
    cudaStreamWaitEvent(s2, evFork, 0);
    k_gemm_mma<128, 128, 0, 0><<<nbM, 256, 0, s2>>>(x, W1, NN);
    cudaEventRecord(evJoin, s2);

    // main stream: CSR build + normalization
    void* pcnt = nullptr;
    cudaGetSymbolAddress(&pcnt, g_cnt);
    cudaMemsetAsync(pcnt, 0, NN * sizeof(int), 0);
    k_hist<<<nbE4, 256>>>(ei, E);
    k_scan_a<<<sb, 1024>>>();
    k_scan_b<<<sb, 1024>>>(sb);
    k_scatter<<<nbE4, 256>>>(ei, E);

    // join, then layer 1 aggregation (applies dinv[s] per edge, fp16 h out)
    cudaStreamWaitEvent(0, evJoin, 0);
    k_agg_h<128, 0><<<nbW, 256>>>(b1);

    // layer 2: 128 -> 64 (fp16 A, 2-term mma, prescaled)
    k_gemm_mma<128, 64, 1, 1><<<nbM, 256>>>(nullptr, W2, NN);
    k_agg_h<64, 1><<<nbW, 256>>>(b2);

    // layer 3: 64 -> 32 (fp16 A, 2-term mma) + fused scoring
    k_gemm_mma<64, 32, 1, 1><<<nbM, 256>>>(nullptr, W3, NN);
    k_agg3_score<<<nbW, 256>>>(b3, Wc);

    // edge scoring
    k_edgeout<<<nbE4, 256>>>(ei, bc, out, E);
}